// round 2
// baseline (speedup 1.0000x reference)
#include <cuda_runtime.h>
#include <math.h>

// Problem constants
#define B    16
#define S    512
#define DIN  512
#define DH   1024
#define NG   4096           // 4 gates * DH, gate-interleaved: n' = col*4 + gate
#define ROWS (B*S)          // 8192
#define NBLK 128            // persistent grid size (<= 148 SMs, all co-resident)

// ---------------- device scratch (static, allocation-free) ----------------
__device__ float g_wp0[DH*NG];    // layer0 recurrent W, packed [k][n']
__device__ float g_wp1[DH*NG];    // layer1 recurrent W
__device__ float g_wx0[DIN*NG];   // layer0 input W
__device__ float g_wx1[DH*NG];    // layer1 input W
__device__ float g_b0p[NG];       // packed biases (gate-interleaved)
__device__ float g_b1p[NG];
__device__ float g_xpre[(size_t)ROWS*NG];   // precomputed input-gate contributions
__device__ float g_h0all[(size_t)ROWS*DH];  // layer0 H for all t  [t][b][col]
__device__ float g_h1all[(size_t)ROWS*DH];  // layer1 H for all t
__device__ float g_hstate[2][B*DH];         // double-buffered H state
__device__ float g_cstate[B*DH];            // C state
__device__ volatile unsigned g_bar;         // monotone grid-barrier counter (reset by init)

struct WPtrs {
    const float* W0[4]; const float* b0[4];
    const float* W1[4]; const float* b1[4];
};

// ---------------- weight packing: gate-interleaved layouts ----------------
__global__ void pack_kernel(WPtrs p) {
    int tid = blockIdx.x * blockDim.x + threadIdx.x;
    if (tid >= DH * NG) return;
    int k   = tid >> 12;      // / 4096
    int np  = tid & 4095;
    int col = np >> 2;
    int g   = np & 3;
    g_wp0[tid] = p.W0[g][(DIN + k) * DH + col];  // H-part rows of layer0 W
    g_wp1[tid] = p.W1[g][(DH  + k) * DH + col];  // H-part rows of layer1 W
    g_wx1[tid] = p.W1[g][k * DH + col];          // x-part rows of layer1 W
    if (k < DIN) g_wx0[(size_t)k * NG + np] = p.W0[g][k * DH + col];
    if (tid < NG) { g_b0p[np] = p.b0[g][col]; g_b1p[np] = p.b1[g][col]; }
}

// ---------------- zero H / C state + barrier counter ----------------
__global__ void init_kernel() {
    int tid = blockIdx.x * blockDim.x + threadIdx.x;
    if (tid < 2 * B * DH)       ((float*)g_hstate)[tid] = 0.f;
    else if (tid < 3 * B * DH)  g_cstate[tid - 2 * B * DH] = 0.f;
    if (tid == 0) g_bar = 0u;
}

// ---------------- batched input GEMM: g_xpre = bias + X @ Wx ----------------
__global__ void __launch_bounds__(256) xpre_kernel(int layer,
                                                   const float* __restrict__ emb,
                                                   const int* __restrict__ tokens) {
    __shared__ float sx[32 * 32];
    __shared__ int stok[32];
    const float* Wx    = layer ? g_wx1 : g_wx0;
    const float* biasp = layer ? g_b1p : g_b0p;
    const int K        = layer ? DH : DIN;

    int tid  = threadIdx.x;
    int w    = tid >> 5, lane = tid & 31;
    int rbase = blockIdx.x * 32;
    int np    = blockIdx.y * 128 + lane * 4;

    if (layer == 0 && tid < 32) {
        int row = rbase + tid;
        int t = row >> 4, b = row & 15;
        stok[tid] = tokens[b * S + t];
    }
    __syncthreads();

    float acc[16];
    #pragma unroll
    for (int i = 0; i < 16; i++) acc[i] = 0.f;

    for (int k0 = 0; k0 < K; k0 += 32) {
        __syncthreads();
        for (int i = tid; i < 1024; i += 256) {
            int r = i >> 5, kk = i & 31;
            float v;
            if (layer == 0) v = emb[(size_t)stok[r] * DIN + k0 + kk];
            else            v = g_h0all[(size_t)(rbase + r) * DH + k0 + kk];
            sx[i] = v;
        }
        __syncthreads();
        #pragma unroll 4
        for (int kk = 0; kk < 32; kk++) {
            float4 wv = *(const float4*)(Wx + (size_t)(k0 + kk) * NG + np);
            #pragma unroll
            for (int r = 0; r < 4; r++) {
                float x = sx[(w * 4 + r) * 32 + kk];
                acc[r * 4 + 0] += x * wv.x;
                acc[r * 4 + 1] += x * wv.y;
                acc[r * 4 + 2] += x * wv.z;
                acc[r * 4 + 3] += x * wv.w;
            }
        }
    }
    float4 bv = *(const float4*)(biasp + np);
    #pragma unroll
    for (int r = 0; r < 4; r++) {
        int row = rbase + w * 4 + r;
        float4 o;
        o.x = acc[r * 4 + 0] + bv.x;
        o.y = acc[r * 4 + 1] + bv.y;
        o.z = acc[r * 4 + 2] + bv.z;
        o.w = acc[r * 4 + 3] + bv.w;
        *(float4*)(g_xpre + (size_t)row * NG + np) = o;
    }
}

// ---------------- persistent recurrent layer ----------------
// 128 blocks x 256 threads, all co-resident. Block bx owns n' in [bx*32, bx*32+32)
// (= 8 hidden cols x 4 gates), all 16 batches, full K=1024 (no cross-block K-split).
// Per step: 4 chunks of 256 k staged in smem (transposed, pad 20), warp w takes its
// 32-k slice of each chunk; lane owns 1 n' with 16 batch accumulators.
// Cross-warp reduce in smem, in-block LSTM finalize, then one grid barrier.
__global__ void __launch_bounds__(256) lstm_persist_kernel(int layer) {
    __shared__ float shT[256 * 20];   // H chunk transposed (5120 floats); reused for reduce

    const float* Wp  = layer ? g_wp1 : g_wp0;
    float* hall_base = layer ? g_h1all : g_h0all;

    const int tid  = threadIdx.x;
    const int w    = tid >> 5, lane = tid & 31;
    const int bx   = blockIdx.x;
    const int np   = bx * 32 + lane;     // owned n' in compute phase
    const int col0 = bx * 8;             // cols covered by this block

    for (int t = 0; t < S; t++) {
        const float* hprev = g_hstate[t & 1];
        float*       hnext = g_hstate[(t & 1) ^ 1];

        float acc[16];
        #pragma unroll
        for (int i = 0; i < 16; i++) acc[i] = 0.f;

        for (int c = 0; c < 4; c++) {
            const int kbase = c * 256;
            __syncthreads();   // protect shT reuse
            // stage H chunk transposed: shT[kl*20 + b]
            for (int i = tid; i < 4096; i += 256) {
                int b = i >> 8, kl = i & 255;
                shT[kl * 20 + b] = hprev[b * DH + kbase + kl];
            }
            __syncthreads();
            const int kw = w * 32;
            #pragma unroll 4
            for (int kk = 0; kk < 32; kk++) {
                int kl = kw + kk;
                float wv = Wp[(size_t)(kbase + kl) * NG + np];
                const float4* hp = (const float4*)(shT + kl * 20);
                float4 h0 = hp[0], h1 = hp[1], h2 = hp[2], h3 = hp[3];
                acc[0]  += h0.x * wv;  acc[1]  += h0.y * wv;
                acc[2]  += h0.z * wv;  acc[3]  += h0.w * wv;
                acc[4]  += h1.x * wv;  acc[5]  += h1.y * wv;
                acc[6]  += h1.z * wv;  acc[7]  += h1.w * wv;
                acc[8]  += h2.x * wv;  acc[9]  += h2.y * wv;
                acc[10] += h2.z * wv;  acc[11] += h2.w * wv;
                acc[12] += h3.x * wv;  acc[13] += h3.y * wv;
                acc[14] += h3.z * wv;  acc[15] += h3.w * wv;
            }
        }

        // cross-warp reduce: shT[(w*32+lane)*16 + b] = acc[b]
        __syncthreads();
        #pragma unroll
        for (int b4 = 0; b4 < 4; b4++) {
            float4 v = make_float4(acc[b4*4+0], acc[b4*4+1], acc[b4*4+2], acc[b4*4+3]);
            *(float4*)(shT + tid * 16 + b4 * 4) = v;
        }
        __syncthreads();

        // finalize: 128 threads, each owns (b, local col cl)
        if (tid < 128) {
            int b  = tid >> 3, cl = tid & 7;
            const float* xq = g_xpre + ((size_t)t * B + b) * NG + bx * 32;
            float ga[4];
            #pragma unroll
            for (int g = 0; g < 4; g++) {
                int nloc = cl * 4 + g;
                float v = xq[nloc];
                #pragma unroll
                for (int ww = 0; ww < 8; ww++)
                    v += shT[(ww * 32 + nloc) * 16 + b];
                ga[g] = v;
            }
            float I = 1.f / (1.f + expf(-ga[0]));
            float F = 1.f / (1.f + expf(-ga[1]));
            float G = tanhf(ga[2]);
            float O = 1.f / (1.f + expf(-ga[3]));
            int col = col0 + cl;
            int ci  = b * DH + col;
            float C = F * g_cstate[ci] + I * G;
            g_cstate[ci] = C;
            float H = O * tanhf(C);
            hnext[ci] = H;
            hall_base[((size_t)t * B + b) * DH + col] = H;
        }

        // grid barrier (monotone counter; reset by init_kernel before launch)
        __syncthreads();
        if (tid == 0) {
            __threadfence();
            atomicAdd((unsigned*)&g_bar, 1u);
            unsigned target = (unsigned)(t + 1) * NBLK;
            while (g_bar < target) { }
            __threadfence();
        }
        __syncthreads();
    }
}

// ---------------- FC head + 2-class log_softmax ----------------
__global__ void __launch_bounds__(256) fc_kernel(const float* __restrict__ Wfc,
                                                 const float* __restrict__ bfc,
                                                 float* __restrict__ out) {
    int tid = threadIdx.x;
    int w = tid >> 5, lane = tid & 31;
    int row = blockIdx.x * 8 + w;
    const float* h = g_h1all + (size_t)row * DH;
    float a0 = 0.f, a1 = 0.f;
    for (int k = lane; k < DH; k += 32) {
        float hv = h[k];
        a0 += hv * Wfc[k * 2 + 0];
        a1 += hv * Wfc[k * 2 + 1];
    }
    #pragma unroll
    for (int off = 16; off; off >>= 1) {
        a0 += __shfl_xor_sync(0xFFFFFFFFu, a0, off);
        a1 += __shfl_xor_sync(0xFFFFFFFFu, a1, off);
    }
    if (lane == 0) {
        float l0 = a0 + bfc[0], l1 = a1 + bfc[1];
        float m  = fmaxf(l0, l1);
        float lse = m + logf(expf(l0 - m) + expf(l1 - m));
        int t = row >> 4, b = row & 15;
        out[((size_t)b * S + t) * 2 + 0] = l0 - lse;
        out[((size_t)b * S + t) * 2 + 1] = l1 - lse;
    }
}

// ---------------- launcher (graph-capturable, allocation-free, 8 nodes) ----------------
extern "C" void kernel_launch(void* const* d_in, const int* in_sizes, int n_in,
                              void* d_out, int out_size) {
    const int*   tokens = (const int*)d_in[0];
    const float* emb    = (const float*)d_in[1];
    WPtrs p;
    for (int g = 0; g < 4; g++) {
        p.W0[g] = (const float*)d_in[2  + g * 2];
        p.b0[g] = (const float*)d_in[3  + g * 2];
        p.W1[g] = (const float*)d_in[10 + g * 2];
        p.b1[g] = (const float*)d_in[11 + g * 2];
    }
    const float* Wfc = (const float*)d_in[18];
    const float* bfc = (const float*)d_in[19];
    float* out = (float*)d_out;

    pack_kernel<<<(DH * NG + 255) / 256, 256>>>(p);

    // ----- layer 0 -----
    init_kernel<<<(3 * B * DH + 255) / 256, 256>>>();
    xpre_kernel<<<dim3(ROWS / 32, NG / 128), 256>>>(0, emb, tokens);
    lstm_persist_kernel<<<NBLK, 256>>>(0);

    // ----- layer 1 -----
    init_kernel<<<(3 * B * DH + 255) / 256, 256>>>();
    xpre_kernel<<<dim3(ROWS / 32, NG / 128), 256>>>(1, emb, tokens);
    lstm_persist_kernel<<<NBLK, 256>>>(1);

    // ----- head -----
    fc_kernel<<<ROWS / 8, 256>>>(Wfc, bfc, out);
}

// round 4
// speedup vs baseline: 1.6598x; 1.6598x over previous
#include <cuda_runtime.h>
#include <math.h>

// Problem constants
#define B    16
#define S    512
#define DIN  512
#define DH   1024
#define NG   4096           // 4 gates * DH, gate-interleaved: n' = col*4 + gate
#define ROWS (B*S)          // 8192
#define NBLK 128            // persistent grid size (<= 148 SMs, all co-resident)
#define TPB  512            // threads per persistent block (16 warps)

// ---------------- device scratch (static, allocation-free) ----------------
__device__ float g_wp0[DH*NG];    // layer0 recurrent W, packed [k][n']
__device__ float g_wp1[DH*NG];    // layer1 recurrent W
__device__ float g_wx0[DIN*NG];   // layer0 input W
__device__ float g_wx1[DH*NG];    // layer1 input W
__device__ float g_b0p[NG];       // packed biases (gate-interleaved)
__device__ float g_b1p[NG];
__device__ float g_xpre[(size_t)ROWS*NG];   // precomputed input-gate contributions
__device__ float g_h0all[(size_t)ROWS*DH];  // layer0 H for all t  [t][b][col]
__device__ float g_h1all[(size_t)ROWS*DH];  // layer1 H for all t
__device__ float g_hstateT[2][DH*B];        // double-buffered H state, TRANSPOSED [k][b]
__device__ float g_cstate[B*DH];            // C state
__device__ volatile unsigned g_bar;         // monotone grid-barrier counter (reset by init)

struct WPtrs {
    const float* W0[4]; const float* b0[4];
    const float* W1[4]; const float* b1[4];
};

// ---------------- weight packing: gate-interleaved layouts ----------------
__global__ void pack_kernel(WPtrs p) {
    int tid = blockIdx.x * blockDim.x + threadIdx.x;
    if (tid >= DH * NG) return;
    int k   = tid >> 12;      // / 4096
    int np  = tid & 4095;
    int col = np >> 2;
    int g   = np & 3;
    g_wp0[tid] = p.W0[g][(DIN + k) * DH + col];  // H-part rows of layer0 W
    g_wp1[tid] = p.W1[g][(DH  + k) * DH + col];  // H-part rows of layer1 W
    g_wx1[tid] = p.W1[g][k * DH + col];          // x-part rows of layer1 W
    if (k < DIN) g_wx0[(size_t)k * NG + np] = p.W0[g][k * DH + col];
    if (tid < NG) { g_b0p[np] = p.b0[g][col]; g_b1p[np] = p.b1[g][col]; }
}

// ---------------- zero H / C state + barrier counter ----------------
__global__ void init_kernel() {
    int tid = blockIdx.x * blockDim.x + threadIdx.x;
    if (tid < 2 * B * DH)       ((float*)g_hstateT)[tid] = 0.f;
    else if (tid < 3 * B * DH)  g_cstate[tid - 2 * B * DH] = 0.f;
    if (tid == 0) g_bar = 0u;
}

// ---------------- batched input GEMM: g_xpre = bias + X @ Wx ----------------
__global__ void __launch_bounds__(256) xpre_kernel(int layer,
                                                   const float* __restrict__ emb,
                                                   const int* __restrict__ tokens) {
    __shared__ float sx[32 * 32];
    __shared__ int stok[32];
    const float* Wx    = layer ? g_wx1 : g_wx0;
    const float* biasp = layer ? g_b1p : g_b0p;
    const int K        = layer ? DH : DIN;

    int tid  = threadIdx.x;
    int w    = tid >> 5, lane = tid & 31;
    int rbase = blockIdx.x * 32;
    int np    = blockIdx.y * 128 + lane * 4;

    if (layer == 0 && tid < 32) {
        int row = rbase + tid;
        int t = row >> 4, b = row & 15;
        stok[tid] = tokens[b * S + t];
    }
    __syncthreads();

    float acc[16];
    #pragma unroll
    for (int i = 0; i < 16; i++) acc[i] = 0.f;

    for (int k0 = 0; k0 < K; k0 += 32) {
        __syncthreads();
        for (int i = tid; i < 1024; i += 256) {
            int r = i >> 5, kk = i & 31;
            float v;
            if (layer == 0) v = emb[(size_t)stok[r] * DIN + k0 + kk];
            else            v = g_h0all[(size_t)(rbase + r) * DH + k0 + kk];
            sx[i] = v;
        }
        __syncthreads();
        #pragma unroll 4
        for (int kk = 0; kk < 32; kk++) {
            float4 wv = *(const float4*)(Wx + (size_t)(k0 + kk) * NG + np);
            #pragma unroll
            for (int r = 0; r < 4; r++) {
                float x = sx[(w * 4 + r) * 32 + kk];
                acc[r * 4 + 0] += x * wv.x;
                acc[r * 4 + 1] += x * wv.y;
                acc[r * 4 + 2] += x * wv.z;
                acc[r * 4 + 3] += x * wv.w;
            }
        }
    }
    float4 bv = *(const float4*)(biasp + np);
    #pragma unroll
    for (int r = 0; r < 4; r++) {
        int row = rbase + w * 4 + r;
        float4 o;
        o.x = acc[r * 4 + 0] + bv.x;
        o.y = acc[r * 4 + 1] + bv.y;
        o.z = acc[r * 4 + 2] + bv.z;
        o.w = acc[r * 4 + 3] + bv.w;
        *(float4*)(g_xpre + (size_t)row * NG + np) = o;
    }
}

// ---------------- persistent recurrent layer (weights-stationary) ----------------
// 128 blocks x 512 threads (16 warps). Block bx owns n' in [bx*32, bx*32+32)
// (8 hidden cols x 4 gates), full K=1024. Warp w owns k-slice of 64
// (32 in each of 2 chunks); each thread holds its 64 weights in REGISTERS,
// loaded once before the time loop -> inner loop is pure FFMA + broadcast LDS.
// H state is kept transposed in global ([k][b]) so staging is a straight
// conflict-free float4 copy. Cross-warp reduce in smem, in-block finalize,
// one monotone grid barrier per step.
__global__ void __launch_bounds__(TPB) lstm_persist_kernel(int layer) {
    __shared__ float sbuf[8192];   // 32KB: H chunk [512][16] during compute; reduce buffer after

    const float* Wp  = layer ? g_wp1 : g_wp0;
    float* hall_base = layer ? g_h1all : g_h0all;

    const int tid  = threadIdx.x;
    const int w    = tid >> 5;
    const int bx   = blockIdx.x;
    const int np   = bx * 32 + (tid & 31);   // owned n'
    const int col0 = bx * 8;                 // cols covered by this block

    // ---- preload weights into registers (one-time) ----
    float Wreg[64];
    #pragma unroll
    for (int c = 0; c < 2; c++)
        #pragma unroll
        for (int j = 0; j < 32; j++)
            Wreg[c * 32 + j] = Wp[(size_t)(c * 512 + w * 32 + j) * NG + np];

    for (int t = 0; t < S; t++) {
        const float* hprevT = g_hstateT[t & 1];
        float*       hnextT = g_hstateT[(t & 1) ^ 1];

        float acc[16];
        #pragma unroll
        for (int i = 0; i < 16; i++) acc[i] = 0.f;

        #pragma unroll
        for (int c = 0; c < 2; c++) {
            __syncthreads();   // protect sbuf reuse
            // stage H chunk: contiguous copy of hprevT[c*512*16 .. +8192)
            {
                const float4* src = (const float4*)(hprevT + c * 8192);
                float4*       dst = (float4*)sbuf;
                #pragma unroll
                for (int i = 0; i < 4; i++)
                    dst[tid + i * TPB] = src[tid + i * TPB];
            }
            __syncthreads();
            const int klocal = w * 32;   // this warp's slice within the 512 chunk
            #pragma unroll
            for (int j = 0; j < 32; j++) {
                float wv = Wreg[c * 32 + j];
                const float4* hp = (const float4*)(sbuf + (klocal + j) * 16);
                float4 h0 = hp[0], h1 = hp[1], h2 = hp[2], h3 = hp[3];
                acc[0]  += h0.x * wv;  acc[1]  += h0.y * wv;
                acc[2]  += h0.z * wv;  acc[3]  += h0.w * wv;
                acc[4]  += h1.x * wv;  acc[5]  += h1.y * wv;
                acc[6]  += h1.z * wv;  acc[7]  += h1.w * wv;
                acc[8]  += h2.x * wv;  acc[9]  += h2.y * wv;
                acc[10] += h2.z * wv;  acc[11] += h2.w * wv;
                acc[12] += h3.x * wv;  acc[13] += h3.y * wv;
                acc[14] += h3.z * wv;  acc[15] += h3.w * wv;
            }
        }

        // cross-warp reduce: sbuf[tid*16 + b] = acc[b]   (exactly 32KB)
        __syncthreads();
        #pragma unroll
        for (int b4 = 0; b4 < 4; b4++)
            *(float4*)(sbuf + tid * 16 + b4 * 4) =
                make_float4(acc[b4*4+0], acc[b4*4+1], acc[b4*4+2], acc[b4*4+3]);
        __syncthreads();

        // finalize: 128 threads; tid -> (b = tid&15, cl = tid>>4)
        if (tid < 128) {
            int b  = tid & 15, cl = tid >> 4;
            const float* xq = g_xpre + ((size_t)t * B + b) * NG + bx * 32;
            float ga[4];
            #pragma unroll
            for (int g = 0; g < 4; g++) {
                int nloc = cl * 4 + g;
                float v = xq[nloc];
                #pragma unroll
                for (int ww = 0; ww < 16; ww++)
                    v += sbuf[(ww * 32 + nloc) * 16 + b];
                ga[g] = v;
            }
            float I = 1.f / (1.f + expf(-ga[0]));
            float F = 1.f / (1.f + expf(-ga[1]));
            float G = tanhf(ga[2]);
            float O = 1.f / (1.f + expf(-ga[3]));
            int col = col0 + cl;
            int ci  = b * DH + col;
            float C = F * g_cstate[ci] + I * G;
            g_cstate[ci] = C;
            float H = O * tanhf(C);
            hnextT[col * 16 + b] = H;                       // transposed state for next step
            hall_base[((size_t)t * B + b) * DH + col] = H;  // row-major history
        }

        // grid barrier (monotone counter; reset by init_kernel before launch)
        __syncthreads();
        if (tid == 0) {
            __threadfence();
            atomicAdd((unsigned*)&g_bar, 1u);
            unsigned target = (unsigned)(t + 1) * NBLK;
            while (g_bar < target) { __nanosleep(64); }
            __threadfence();
        }
        __syncthreads();
    }
}

// ---------------- FC head + 2-class log_softmax ----------------
__global__ void __launch_bounds__(256) fc_kernel(const float* __restrict__ Wfc,
                                                 const float* __restrict__ bfc,
                                                 float* __restrict__ out) {
    int tid = threadIdx.x;
    int w = tid >> 5, lane = tid & 31;
    int row = blockIdx.x * 8 + w;
    const float* h = g_h1all + (size_t)row * DH;
    float a0 = 0.f, a1 = 0.f;
    for (int k = lane; k < DH; k += 32) {
        float hv = h[k];
        a0 += hv * Wfc[k * 2 + 0];
        a1 += hv * Wfc[k * 2 + 1];
    }
    #pragma unroll
    for (int off = 16; off; off >>= 1) {
        a0 += __shfl_xor_sync(0xFFFFFFFFu, a0, off);
        a1 += __shfl_xor_sync(0xFFFFFFFFu, a1, off);
    }
    if (lane == 0) {
        float l0 = a0 + bfc[0], l1 = a1 + bfc[1];
        float m  = fmaxf(l0, l1);
        float lse = m + logf(expf(l0 - m) + expf(l1 - m));
        int t = row >> 4, b = row & 15;
        out[((size_t)b * S + t) * 2 + 0] = l0 - lse;
        out[((size_t)b * S + t) * 2 + 1] = l1 - lse;
    }
}

// ---------------- launcher (graph-capturable, allocation-free, 8 nodes) ----------------
extern "C" void kernel_launch(void* const* d_in, const int* in_sizes, int n_in,
                              void* d_out, int out_size) {
    const int*   tokens = (const int*)d_in[0];
    const float* emb    = (const float*)d_in[1];
    WPtrs p;
    for (int g = 0; g < 4; g++) {
        p.W0[g] = (const float*)d_in[2  + g * 2];
        p.b0[g] = (const float*)d_in[3  + g * 2];
        p.W1[g] = (const float*)d_in[10 + g * 2];
        p.b1[g] = (const float*)d_in[11 + g * 2];
    }
    const float* Wfc = (const float*)d_in[18];
    const float* bfc = (const float*)d_in[19];
    float* out = (float*)d_out;

    pack_kernel<<<(DH * NG + 255) / 256, 256>>>(p);

    // ----- layer 0 -----
    init_kernel<<<(3 * B * DH + 255) / 256, 256>>>();
    xpre_kernel<<<dim3(ROWS / 32, NG / 128), 256>>>(0, emb, tokens);
    lstm_persist_kernel<<<NBLK, TPB>>>(0);

    // ----- layer 1 -----
    init_kernel<<<(3 * B * DH + 255) / 256, 256>>>();
    xpre_kernel<<<dim3(ROWS / 32, NG / 128), 256>>>(1, emb, tokens);
    lstm_persist_kernel<<<NBLK, TPB>>>(1);

    // ----- head -----
    fc_kernel<<<ROWS / 8, 256>>>(Wfc, bfc, out);
}

// round 5
// speedup vs baseline: 1.7312x; 1.0430x over previous
#include <cuda_runtime.h>
#include <math.h>

// Problem constants
#define B    16
#define S    512
#define DIN  512
#define DH   1024
#define NG   4096           // 4 gates * DH, gate-interleaved: n' = col*4 + gate
#define ROWS (B*S)          // 8192
#define NBLK 128            // persistent grid size (<= 148 SMs, all co-resident)
#define TPB  512            // threads per persistent block (16 warps)

// xpre GEMM tiling
#define TM 128              // rows per block
#define TN 64               // n' per block
#define KC 32               // k chunk
#define XS 36               // padded smem stride for X tile (keeps 16B alignment)

// ---------------- device scratch (static, allocation-free) ----------------
__device__ float g_wp0[DH*NG];    // layer0 recurrent W, packed [k][n']
__device__ float g_wp1[DH*NG];    // layer1 recurrent W
__device__ float g_wx0[DIN*NG];   // layer0 input W
__device__ float g_wx1[DH*NG];    // layer1 input W
__device__ float g_b0p[NG];       // packed biases (gate-interleaved)
__device__ float g_b1p[NG];
__device__ float g_xpre[(size_t)ROWS*NG];   // precomputed input-gate contributions
__device__ float g_h0all[(size_t)ROWS*DH];  // layer0 H for all t  [t][b][col]
__device__ float g_h1all[(size_t)ROWS*DH];  // layer1 H for all t
__device__ float g_hstateT[2][DH*B];        // double-buffered H state, TRANSPOSED [k][b]
__device__ float g_cstate[B*DH];            // C state
__device__ volatile unsigned g_bar;         // monotone grid-barrier counter (reset by init)

struct WPtrs {
    const float* W0[4]; const float* b0[4];
    const float* W1[4]; const float* b1[4];
};

// ---------------- weight packing: gate-interleaved layouts ----------------
__global__ void pack_kernel(WPtrs p) {
    int tid = blockIdx.x * blockDim.x + threadIdx.x;
    if (tid >= DH * NG) return;
    int k   = tid >> 12;      // / 4096
    int np  = tid & 4095;
    int col = np >> 2;
    int g   = np & 3;
    g_wp0[tid] = p.W0[g][(DIN + k) * DH + col];  // H-part rows of layer0 W
    g_wp1[tid] = p.W1[g][(DH  + k) * DH + col];  // H-part rows of layer1 W
    g_wx1[tid] = p.W1[g][k * DH + col];          // x-part rows of layer1 W
    if (k < DIN) g_wx0[(size_t)k * NG + np] = p.W0[g][k * DH + col];
    if (tid < NG) { g_b0p[np] = p.b0[g][col]; g_b1p[np] = p.b1[g][col]; }
}

// ---------------- zero H / C state + barrier counter ----------------
__global__ void init_kernel() {
    int tid = blockIdx.x * blockDim.x + threadIdx.x;
    if (tid < 2 * B * DH)       ((float*)g_hstateT)[tid] = 0.f;
    else if (tid < 3 * B * DH)  g_cstate[tid - 2 * B * DH] = 0.f;
    if (tid == 0) g_bar = 0u;
}

// ---------------- batched input GEMM: g_xpre = bias + X @ Wx ----------------
// 128x64 tile per block, 256 threads, 8x8 register outer product per thread.
// X and W staged in smem per 32-k chunk with register-prefetch pipeline.
// layer 0: X = emb[tokens] (gather, K=512); layer 1: X = g_h0all (K=1024).
__global__ void __launch_bounds__(256) xpre_kernel(int layer,
                                                   const float* __restrict__ emb,
                                                   const int* __restrict__ tokens) {
    __shared__ float sX[TM * XS];      // [row][k], stride 36
    __shared__ float sW[KC * TN];      // [k][n']
    __shared__ int   stok[TM];

    const float* Wx    = layer ? g_wx1 : g_wx0;
    const float* biasp = layer ? g_b1p : g_b0p;
    const int K        = layer ? DH : DIN;
    const int NCH      = K / KC;

    const int tid   = threadIdx.x;
    const int ty    = tid >> 4;         // 0..15
    const int tx    = tid & 15;         // 0..15
    const int rbase = blockIdx.x * TM;
    const int nbase = blockIdx.y * TN;

    if (layer == 0 && tid < TM) {
        int row = rbase + tid;
        stok[tid] = tokens[(row & 15) * S + (row >> 4)];
    }
    if (layer == 0) __syncthreads();

    // staging index precompute
    // X: f = tid + j*256 (j<4): rloc = f>>3, kq = (f&7)*4
    // W: f = tid + j*256 (j<2): kw = f>>4,  nq = (f&15)*4
    float4 xr[4], wr[2];

    // preload chunk 0
    {
        #pragma unroll
        for (int j = 0; j < 4; j++) {
            int f = tid + j * 256, rloc = f >> 3, kq = (f & 7) * 4;
            const float* src = (layer == 0)
                ? (emb + (size_t)stok[rloc] * DIN + kq)
                : (g_h0all + (size_t)(rbase + rloc) * DH + kq);
            xr[j] = *(const float4*)src;
        }
        #pragma unroll
        for (int j = 0; j < 2; j++) {
            int f = tid + j * 256, kw = f >> 4, nq = (f & 15) * 4;
            wr[j] = *(const float4*)(Wx + (size_t)kw * NG + nbase + nq);
        }
    }

    float acc[8][8];
    #pragma unroll
    for (int i = 0; i < 8; i++)
        #pragma unroll
        for (int j = 0; j < 8; j++) acc[i][j] = 0.f;

    for (int c = 0; c < NCH; c++) {
        __syncthreads();
        // store staged regs to smem
        #pragma unroll
        for (int j = 0; j < 4; j++) {
            int f = tid + j * 256, rloc = f >> 3, kq = (f & 7) * 4;
            *(float4*)(sX + rloc * XS + kq) = xr[j];
        }
        #pragma unroll
        for (int j = 0; j < 2; j++) {
            int f = tid + j * 256, kw = f >> 4, nq = (f & 15) * 4;
            *(float4*)(sW + kw * TN + nq) = wr[j];
        }
        __syncthreads();

        // prefetch next chunk while computing this one
        if (c + 1 < NCH) {
            int k0 = (c + 1) * KC;
            #pragma unroll
            for (int j = 0; j < 4; j++) {
                int f = tid + j * 256, rloc = f >> 3, kq = (f & 7) * 4;
                const float* src = (layer == 0)
                    ? (emb + (size_t)stok[rloc] * DIN + k0 + kq)
                    : (g_h0all + (size_t)(rbase + rloc) * DH + k0 + kq);
                xr[j] = *(const float4*)src;
            }
            #pragma unroll
            for (int j = 0; j < 2; j++) {
                int f = tid + j * 256, kw = f >> 4, nq = (f & 15) * 4;
                wr[j] = *(const float4*)(Wx + (size_t)(k0 + kw) * NG + nbase + nq);
            }
        }

        // 8x8 outer-product over the chunk
        #pragma unroll
        for (int kk = 0; kk < KC; kk++) {
            float xv[8];
            #pragma unroll
            for (int i = 0; i < 8; i++)
                xv[i] = sX[(ty * 8 + i) * XS + kk];
            float4 w0 = *(const float4*)(sW + kk * TN + tx * 8);
            float4 w1 = *(const float4*)(sW + kk * TN + tx * 8 + 4);
            #pragma unroll
            for (int i = 0; i < 8; i++) {
                acc[i][0] += xv[i] * w0.x;
                acc[i][1] += xv[i] * w0.y;
                acc[i][2] += xv[i] * w0.z;
                acc[i][3] += xv[i] * w0.w;
                acc[i][4] += xv[i] * w1.x;
                acc[i][5] += xv[i] * w1.y;
                acc[i][6] += xv[i] * w1.z;
                acc[i][7] += xv[i] * w1.w;
            }
        }
    }

    // epilogue: add bias, write out
    float4 bv0 = *(const float4*)(biasp + nbase + tx * 8);
    float4 bv1 = *(const float4*)(biasp + nbase + tx * 8 + 4);
    #pragma unroll
    for (int i = 0; i < 8; i++) {
        int row = rbase + ty * 8 + i;
        float* dst = g_xpre + (size_t)row * NG + nbase + tx * 8;
        float4 o0, o1;
        o0.x = acc[i][0] + bv0.x; o0.y = acc[i][1] + bv0.y;
        o0.z = acc[i][2] + bv0.z; o0.w = acc[i][3] + bv0.w;
        o1.x = acc[i][4] + bv1.x; o1.y = acc[i][5] + bv1.y;
        o1.z = acc[i][6] + bv1.z; o1.w = acc[i][7] + bv1.w;
        *(float4*)dst       = o0;
        *(float4*)(dst + 4) = o1;
    }
}

// ---------------- persistent recurrent layer (weights-stationary) ----------------
__global__ void __launch_bounds__(TPB) lstm_persist_kernel(int layer) {
    __shared__ float sbuf[8192];   // 32KB: H chunk [512][16] during compute; reduce buffer after

    const float* Wp  = layer ? g_wp1 : g_wp0;
    float* hall_base = layer ? g_h1all : g_h0all;

    const int tid  = threadIdx.x;
    const int w    = tid >> 5;
    const int bx   = blockIdx.x;
    const int np   = bx * 32 + (tid & 31);   // owned n'
    const int col0 = bx * 8;                 // cols covered by this block

    // ---- preload weights into registers (one-time) ----
    float Wreg[64];
    #pragma unroll
    for (int c = 0; c < 2; c++)
        #pragma unroll
        for (int j = 0; j < 32; j++)
            Wreg[c * 32 + j] = Wp[(size_t)(c * 512 + w * 32 + j) * NG + np];

    for (int t = 0; t < S; t++) {
        const float* hprevT = g_hstateT[t & 1];
        float*       hnextT = g_hstateT[(t & 1) ^ 1];

        float acc[16];
        #pragma unroll
        for (int i = 0; i < 16; i++) acc[i] = 0.f;

        #pragma unroll
        for (int c = 0; c < 2; c++) {
            __syncthreads();   // protect sbuf reuse
            {
                const float4* src = (const float4*)(hprevT + c * 8192);
                float4*       dst = (float4*)sbuf;
                #pragma unroll
                for (int i = 0; i < 4; i++)
                    dst[tid + i * TPB] = src[tid + i * TPB];
            }
            __syncthreads();
            const int klocal = w * 32;
            #pragma unroll
            for (int j = 0; j < 32; j++) {
                float wv = Wreg[c * 32 + j];
                const float4* hp = (const float4*)(sbuf + (klocal + j) * 16);
                float4 h0 = hp[0], h1 = hp[1], h2 = hp[2], h3 = hp[3];
                acc[0]  += h0.x * wv;  acc[1]  += h0.y * wv;
                acc[2]  += h0.z * wv;  acc[3]  += h0.w * wv;
                acc[4]  += h1.x * wv;  acc[5]  += h1.y * wv;
                acc[6]  += h1.z * wv;  acc[7]  += h1.w * wv;
                acc[8]  += h2.x * wv;  acc[9]  += h2.y * wv;
                acc[10] += h2.z * wv;  acc[11] += h2.w * wv;
                acc[12] += h3.x * wv;  acc[13] += h3.y * wv;
                acc[14] += h3.z * wv;  acc[15] += h3.w * wv;
            }
        }

        // cross-warp reduce
        __syncthreads();
        #pragma unroll
        for (int b4 = 0; b4 < 4; b4++)
            *(float4*)(sbuf + tid * 16 + b4 * 4) =
                make_float4(acc[b4*4+0], acc[b4*4+1], acc[b4*4+2], acc[b4*4+3]);
        __syncthreads();

        // finalize
        if (tid < 128) {
            int b  = tid & 15, cl = tid >> 4;
            const float* xq = g_xpre + ((size_t)t * B + b) * NG + bx * 32;
            float ga[4];
            #pragma unroll
            for (int g = 0; g < 4; g++) {
                int nloc = cl * 4 + g;
                float v = xq[nloc];
                #pragma unroll
                for (int ww = 0; ww < 16; ww++)
                    v += sbuf[(ww * 32 + nloc) * 16 + b];
                ga[g] = v;
            }
            float I = 1.f / (1.f + expf(-ga[0]));
            float F = 1.f / (1.f + expf(-ga[1]));
            float G = tanhf(ga[2]);
            float O = 1.f / (1.f + expf(-ga[3]));
            int col = col0 + cl;
            int ci  = b * DH + col;
            float C = F * g_cstate[ci] + I * G;
            g_cstate[ci] = C;
            float H = O * tanhf(C);
            hnextT[col * 16 + b] = H;
            hall_base[((size_t)t * B + b) * DH + col] = H;
        }

        // grid barrier
        __syncthreads();
        if (tid == 0) {
            __threadfence();
            atomicAdd((unsigned*)&g_bar, 1u);
            unsigned target = (unsigned)(t + 1) * NBLK;
            while (g_bar < target) { __nanosleep(64); }
            __threadfence();
        }
        __syncthreads();
    }
}

// ---------------- FC head + 2-class log_softmax ----------------
__global__ void __launch_bounds__(256) fc_kernel(const float* __restrict__ Wfc,
                                                 const float* __restrict__ bfc,
                                                 float* __restrict__ out) {
    int tid = threadIdx.x;
    int w = tid >> 5, lane = tid & 31;
    int row = blockIdx.x * 8 + w;
    const float* h = g_h1all + (size_t)row * DH;
    float a0 = 0.f, a1 = 0.f;
    for (int k = lane; k < DH; k += 32) {
        float hv = h[k];
        a0 += hv * Wfc[k * 2 + 0];
        a1 += hv * Wfc[k * 2 + 1];
    }
    #pragma unroll
    for (int off = 16; off; off >>= 1) {
        a0 += __shfl_xor_sync(0xFFFFFFFFu, a0, off);
        a1 += __shfl_xor_sync(0xFFFFFFFFu, a1, off);
    }
    if (lane == 0) {
        float l0 = a0 + bfc[0], l1 = a1 + bfc[1];
        float m  = fmaxf(l0, l1);
        float lse = m + logf(expf(l0 - m) + expf(l1 - m));
        int t = row >> 4, b = row & 15;
        out[((size_t)b * S + t) * 2 + 0] = l0 - lse;
        out[((size_t)b * S + t) * 2 + 1] = l1 - lse;
    }
}

// ---------------- launcher (graph-capturable, allocation-free, 8 nodes) ----------------
extern "C" void kernel_launch(void* const* d_in, const int* in_sizes, int n_in,
                              void* d_out, int out_size) {
    const int*   tokens = (const int*)d_in[0];
    const float* emb    = (const float*)d_in[1];
    WPtrs p;
    for (int g = 0; g < 4; g++) {
        p.W0[g] = (const float*)d_in[2  + g * 2];
        p.b0[g] = (const float*)d_in[3  + g * 2];
        p.W1[g] = (const float*)d_in[10 + g * 2];
        p.b1[g] = (const float*)d_in[11 + g * 2];
    }
    const float* Wfc = (const float*)d_in[18];
    const float* bfc = (const float*)d_in[19];
    float* out = (float*)d_out;

    pack_kernel<<<(DH * NG + 255) / 256, 256>>>(p);

    // ----- layer 0 -----
    init_kernel<<<(3 * B * DH + 255) / 256, 256>>>();
    xpre_kernel<<<dim3(ROWS / TM, NG / TN), 256>>>(0, emb, tokens);
    lstm_persist_kernel<<<NBLK, TPB>>>(0);

    // ----- layer 1 -----
    init_kernel<<<(3 * B * DH + 255) / 256, 256>>>();
    xpre_kernel<<<dim3(ROWS / TM, NG / TN), 256>>>(1, emb, tokens);
    lstm_persist_kernel<<<NBLK, TPB>>>(1);

    // ----- head -----
    fc_kernel<<<ROWS / 8, 256>>>(Wfc, bfc, out);
}

// round 7
// speedup vs baseline: 2.2082x; 1.2756x over previous
#include <cuda_runtime.h>
#include <cuda_bf16.h>
#include <math.h>
#include <stdint.h>

// Problem constants
#define B    16
#define S    512
#define DIN  512
#define DH   1024
#define NG   4096           // 4 gates * DH, gate-interleaved: n' = col*4 + gate
#define ROWS (B*S)          // 8192
#define NBLK 128            // persistent grid size
#define TPB  512            // threads per persistent block (16 warps)

// ---------------- device scratch (static, allocation-free) ----------------
__device__ float g_wp0[DH*NG];    // layer0 recurrent W, packed [k][n'] (fp32, persist kernel)
__device__ float g_wp1[DH*NG];    // layer1 recurrent W
__device__ float g_b0p[NG];       // packed biases (gate-interleaved)
__device__ float g_b1p[NG];
__device__ __nv_bfloat16 g_wbh0[(size_t)NG*DIN];  // layer0 input W, K-major [n'][k], hi
__device__ __nv_bfloat16 g_wbl0[(size_t)NG*DIN];  // lo
__device__ __nv_bfloat16 g_wbh1[(size_t)NG*DH];   // layer1 input W hi
__device__ __nv_bfloat16 g_wbl1[(size_t)NG*DH];   // lo
__device__ __nv_bfloat16 g_xh[(size_t)ROWS*DH];   // X hi ([row][k], stride = layer K)
__device__ __nv_bfloat16 g_xl[(size_t)ROWS*DH];   // X lo
__device__ float g_xpre[(size_t)ROWS*NG];   // precomputed input-gate contributions
__device__ float g_h0all[(size_t)ROWS*DH];  // layer0 H for all t  [t*B+b][col]
__device__ float g_h1all[(size_t)ROWS*DH];  // layer1 H
__device__ float g_hstateT[2][DH*B];        // double-buffered H state, TRANSPOSED [k][b]
__device__ float g_cstate[B*DH];            // C state
__device__ volatile unsigned g_bar;         // monotone grid-barrier counter

struct WPtrs {
    const float* W0[4]; const float* b0[4];
    const float* W1[4]; const float* b1[4];
};

// ================= warp-MMA helpers (sm_80+ PTX, legal on base sm_103) =================
__device__ __forceinline__ uint32_t smem_u32(const void* p) {
    uint32_t a;
    asm("{ .reg .u64 t; cvta.to.shared.u64 t, %1; cvt.u32.u64 %0, t; }" : "=r"(a) : "l"(p));
    return a;
}
__device__ __forceinline__ void ldm_x4(uint32_t* r, uint32_t addr) {
    asm volatile("ldmatrix.sync.aligned.m8n8.x4.shared.b16 {%0,%1,%2,%3}, [%4];"
                 : "=r"(r[0]), "=r"(r[1]), "=r"(r[2]), "=r"(r[3]) : "r"(addr));
}
__device__ __forceinline__ void mma_bf16(float* d, const uint32_t* a, const uint32_t* b) {
    asm volatile("mma.sync.aligned.m16n8k16.row.col.f32.bf16.bf16.f32 "
                 "{%0,%1,%2,%3}, {%4,%5,%6,%7}, {%8,%9}, {%0,%1,%2,%3};"
                 : "+f"(d[0]), "+f"(d[1]), "+f"(d[2]), "+f"(d[3])
                 : "r"(a[0]), "r"(a[1]), "r"(a[2]), "r"(a[3]), "r"(b[0]), "r"(b[1]));
}
static __device__ __forceinline__ uint32_t sw128(uint32_t x) { return x ^ ((x >> 3) & 0x70); }

// ---------------- weight packing: fp32 recurrent (persist) + biases ----------------
__global__ void pack_kernel(WPtrs p) {
    int tid = blockIdx.x * blockDim.x + threadIdx.x;
    if (tid >= DH * NG) return;
    int k   = tid >> 12;
    int np  = tid & 4095;
    int col = np >> 2;
    int g   = np & 3;
    g_wp0[tid] = p.W0[g][(DIN + k) * DH + col];
    g_wp1[tid] = p.W1[g][(DH  + k) * DH + col];
    if (tid < NG) { g_b0p[np] = p.b0[g][col]; g_b1p[np] = p.b1[g][col]; }
}

// ---------------- bf16 hi/lo pack of input weights, K-major [n'][k] ----------------
__global__ void packw_bf16_kernel(WPtrs p, int layer) {
    const int K = layer ? DH : DIN;
    int tid = blockIdx.x * blockDim.x + threadIdx.x;
    if (tid >= NG * K) return;
    int np = tid / K, k = tid % K;
    int col = np >> 2, g = np & 3;
    float w = layer ? p.W1[g][k * DH + col] : p.W0[g][k * DH + col];
    __nv_bfloat16 hi = __float2bfloat16(w);
    __nv_bfloat16 lo = __float2bfloat16(w - __bfloat162float(hi));
    if (layer) { g_wbh1[tid] = hi; g_wbl1[tid] = lo; }
    else       { g_wbh0[tid] = hi; g_wbl0[tid] = lo; }
}

// ---------------- X hi/lo conversion ----------------
__global__ void xcvt_kernel(int layer, const float* __restrict__ emb,
                            const int* __restrict__ tokens) {
    const int K = layer ? DH : DIN;
    long long tid = (long long)blockIdx.x * blockDim.x + threadIdx.x;
    if (tid >= (long long)ROWS * K) return;
    int row = (int)(tid / K), k = (int)(tid % K);
    float v;
    if (layer == 0) {
        int b = row & 15, t = row >> 4;
        v = emb[(size_t)tokens[b * S + t] * DIN + k];
    } else {
        v = g_h0all[(size_t)row * DH + k];
    }
    __nv_bfloat16 hi = __float2bfloat16(v);
    __nv_bfloat16 lo = __float2bfloat16(v - __bfloat162float(hi));
    g_xh[(size_t)row * K + k] = hi;
    g_xl[(size_t)row * K + k] = lo;
}

// ---------------- zero H / C state + barrier counter ----------------
__global__ void init_kernel() {
    int tid = blockIdx.x * blockDim.x + threadIdx.x;
    if (tid < 2 * B * DH)       ((float*)g_hstateT)[tid] = 0.f;
    else if (tid < 3 * B * DH)  g_cstate[tid - 2 * B * DH] = 0.f;
    if (tid == 0) g_bar = 0u;
}

// ---------------- HMMA xpre GEMM: g_xpre = bias + X @ Wx (bf16 hi/lo x3) ----------------
// Block tile M=128 x N=64, K chunks of 64 staged in sw128 smem, reg-prefetch pipeline.
// 8 warps = 4(M) x 2(N); warp tile 32x32; mma.sync m16n8k16 bf16.
// 3 passes Xhi*Whi + Xlo*Whi + Xhi*Wlo accumulated in fp32 regs.
__global__ void __launch_bounds__(256) mma_xpre_kernel(int layer) {
    __shared__ __align__(128) char sAraw[128 * 128];   // 16KB: A tile, 128 rows x 128B
    __shared__ __align__(128) char sBraw[64 * 128];    // 8KB:  B tile,  64 rows x 128B

    const int K = layer ? DH : DIN;
    const __nv_bfloat16* Wh = layer ? g_wbh1 : g_wbh0;
    const __nv_bfloat16* Wl = layer ? g_wbl1 : g_wbl0;
    const float* biasp = layer ? g_b1p : g_b0p;

    const int tid  = threadIdx.x, wid = tid >> 5, lane = tid & 31;
    const int rbase = blockIdx.x * 128;
    const int nbase = blockIdx.y * 64;
    const int wm = wid >> 1, wn = wid & 1;

    const uint32_t sAb = smem_u32(sAraw), sBb = smem_u32(sBraw);

    // ldmatrix row/col-unit bases
    const int ra0 = wm * 32 + (lane & 7) + (lane & 8);           // A: + mt*16
    const int rb0 = wn * 32 + (lane & 7) + (((lane >> 4) & 1) * 8); // B: + nt2*16
    const int ua  = (lane >> 4);          // A col unit: + s*2
    const int ub  = ((lane >> 3) & 1);    // B col unit: + s*2

    float acc[2][4][4];
    #pragma unroll
    for (int i = 0; i < 2; i++)
        #pragma unroll
        for (int j = 0; j < 4; j++)
            #pragma unroll
            for (int q = 0; q < 4; q++) acc[i][j][q] = 0.f;

    const int nch = K / 64;
    const int total = 3 * nch;

    uint4 xr[4], wr[2];
    // preload chunk 0 (pass 0: Xhi * Whi)
    {
        #pragma unroll
        for (int j = 0; j < 4; j++) {
            int gidx = j * 256 + tid, r = gidx >> 3, kg = gidx & 7;
            xr[j] = *(const uint4*)(g_xh + (size_t)(rbase + r) * K + kg * 8);
        }
        #pragma unroll
        for (int j = 0; j < 2; j++) {
            int gidx = j * 256 + tid, r = gidx >> 3, kg = gidx & 7;
            wr[j] = *(const uint4*)(Wh + (size_t)(nbase + r) * K + kg * 8);
        }
    }

    int p = 0, kc = 0;
    for (int it = 0; it < total; it++) {
        // store staged chunk to swizzled smem
        #pragma unroll
        for (int j = 0; j < 4; j++) {
            int gidx = j * 256 + tid, r = gidx >> 3, kg = gidx & 7;
            *(uint4*)(sAraw + sw128((uint32_t)(r * 128 + kg * 16))) = xr[j];
        }
        #pragma unroll
        for (int j = 0; j < 2; j++) {
            int gidx = j * 256 + tid, r = gidx >> 3, kg = gidx & 7;
            *(uint4*)(sBraw + sw128((uint32_t)(r * 128 + kg * 16))) = wr[j];
        }
        __syncthreads();

        // prefetch next chunk
        int np2 = p, nkc = kc + 1;
        if (nkc == nch) { nkc = 0; np2 = p + 1; }
        if (it + 1 < total) {
            const __nv_bfloat16* Asrc = (np2 == 1) ? g_xl : g_xh;
            const __nv_bfloat16* Bsrc = (np2 == 2) ? Wl : Wh;
            const int koff = nkc * 64;
            #pragma unroll
            for (int j = 0; j < 4; j++) {
                int gidx = j * 256 + tid, r = gidx >> 3, kg = gidx & 7;
                xr[j] = *(const uint4*)(Asrc + (size_t)(rbase + r) * K + koff + kg * 8);
            }
            #pragma unroll
            for (int j = 0; j < 2; j++) {
                int gidx = j * 256 + tid, r = gidx >> 3, kg = gidx & 7;
                wr[j] = *(const uint4*)(Bsrc + (size_t)(nbase + r) * K + koff + kg * 8);
            }
        }

        // compute: 4 k16-steps over the 64-k chunk
        #pragma unroll
        for (int s = 0; s < 4; s++) {
            uint32_t a0[4], a1[4], b0[4], b1[4];
            ldm_x4(a0, sAb + sw128((uint32_t)( ra0       * 128 + (s * 2 + ua) * 16)));
            ldm_x4(a1, sAb + sw128((uint32_t)((ra0 + 16) * 128 + (s * 2 + ua) * 16)));
            ldm_x4(b0, sBb + sw128((uint32_t)( rb0       * 128 + (s * 2 + ub) * 16)));
            ldm_x4(b1, sBb + sw128((uint32_t)((rb0 + 16) * 128 + (s * 2 + ub) * 16)));
            mma_bf16(acc[0][0], a0, b0 + 0);
            mma_bf16(acc[0][1], a0, b0 + 2);
            mma_bf16(acc[0][2], a0, b1 + 0);
            mma_bf16(acc[0][3], a0, b1 + 2);
            mma_bf16(acc[1][0], a1, b0 + 0);
            mma_bf16(acc[1][1], a1, b0 + 2);
            mma_bf16(acc[1][2], a1, b1 + 0);
            mma_bf16(acc[1][3], a1, b1 + 2);
        }
        __syncthreads();
        p = np2; kc = nkc;
    }

    // epilogue: d-frag (lane>>2, (lane&3)*2) rows +0/+8
    #pragma unroll
    for (int mt = 0; mt < 2; mt++) {
        #pragma unroll
        for (int nt = 0; nt < 4; nt++) {
            int r = rbase + wm * 32 + mt * 16 + (lane >> 2);
            int c = nbase + wn * 32 + nt * 8 + (lane & 3) * 2;
            float bv0 = biasp[c], bv1 = biasp[c + 1];
            float2 o0 = make_float2(acc[mt][nt][0] + bv0, acc[mt][nt][1] + bv1);
            float2 o1 = make_float2(acc[mt][nt][2] + bv0, acc[mt][nt][3] + bv1);
            *(float2*)(g_xpre + (size_t)r * NG + c)       = o0;
            *(float2*)(g_xpre + (size_t)(r + 8) * NG + c) = o1;
        }
    }
}

// ---------------- persistent recurrent layer (weights-stationary) ----------------
__global__ void __launch_bounds__(TPB) lstm_persist_kernel(int layer) {
    __shared__ float sbuf[8192];

    const float* Wp  = layer ? g_wp1 : g_wp0;
    float* hall_base = layer ? g_h1all : g_h0all;

    const int tid  = threadIdx.x;
    const int w    = tid >> 5;
    const int bx   = blockIdx.x;
    const int np   = bx * 32 + (tid & 31);
    const int col0 = bx * 8;

    float Wreg[64];
    #pragma unroll
    for (int c = 0; c < 2; c++)
        #pragma unroll
        for (int j = 0; j < 32; j++)
            Wreg[c * 32 + j] = Wp[(size_t)(c * 512 + w * 32 + j) * NG + np];

    for (int t = 0; t < S; t++) {
        const float* hprevT = g_hstateT[t & 1];
        float*       hnextT = g_hstateT[(t & 1) ^ 1];

        float acc[16];
        #pragma unroll
        for (int i = 0; i < 16; i++) acc[i] = 0.f;

        #pragma unroll
        for (int c = 0; c < 2; c++) {
            __syncthreads();
            {
                const float4* src = (const float4*)(hprevT + c * 8192);
                float4*       dst = (float4*)sbuf;
                #pragma unroll
                for (int i = 0; i < 4; i++)
                    dst[tid + i * TPB] = src[tid + i * TPB];
            }
            __syncthreads();
            const int klocal = w * 32;
            #pragma unroll
            for (int j = 0; j < 32; j++) {
                float wv = Wreg[c * 32 + j];
                const float4* hp = (const float4*)(sbuf + (klocal + j) * 16);
                float4 h0 = hp[0], h1 = hp[1], h2 = hp[2], h3 = hp[3];
                acc[0]  += h0.x * wv;  acc[1]  += h0.y * wv;
                acc[2]  += h0.z * wv;  acc[3]  += h0.w * wv;
                acc[4]  += h1.x * wv;  acc[5]  += h1.y * wv;
                acc[6]  += h1.z * wv;  acc[7]  += h1.w * wv;
                acc[8]  += h2.x * wv;  acc[9]  += h2.y * wv;
                acc[10] += h2.z * wv;  acc[11] += h2.w * wv;
                acc[12] += h3.x * wv;  acc[13] += h3.y * wv;
                acc[14] += h3.z * wv;  acc[15] += h3.w * wv;
            }
        }

        __syncthreads();
        #pragma unroll
        for (int b4 = 0; b4 < 4; b4++)
            *(float4*)(sbuf + tid * 16 + b4 * 4) =
                make_float4(acc[b4*4+0], acc[b4*4+1], acc[b4*4+2], acc[b4*4+3]);
        __syncthreads();

        if (tid < 128) {
            int b  = tid & 15, cl = tid >> 4;
            const float* xq = g_xpre + ((size_t)t * B + b) * NG + bx * 32;
            float ga[4];
            #pragma unroll
            for (int g = 0; g < 4; g++) {
                int nloc = cl * 4 + g;
                float v = xq[nloc];
                #pragma unroll
                for (int ww = 0; ww < 16; ww++)
                    v += sbuf[(ww * 32 + nloc) * 16 + b];
                ga[g] = v;
            }
            float I = 1.f / (1.f + expf(-ga[0]));
            float F = 1.f / (1.f + expf(-ga[1]));
            float G = tanhf(ga[2]);
            float O = 1.f / (1.f + expf(-ga[3]));
            int col = col0 + cl;
            int ci  = b * DH + col;
            float C = F * g_cstate[ci] + I * G;
            g_cstate[ci] = C;
            float H = O * tanhf(C);
            hnextT[col * 16 + b] = H;
            hall_base[((size_t)t * B + b) * DH + col] = H;
        }

        __syncthreads();
        if (tid == 0) {
            __threadfence();
            atomicAdd((unsigned*)&g_bar, 1u);
            unsigned target = (unsigned)(t + 1) * NBLK;
            while (g_bar < target) { }
            __threadfence();
        }
        __syncthreads();
    }
}

// ---------------- FC head + 2-class log_softmax ----------------
__global__ void __launch_bounds__(256) fc_kernel(const float* __restrict__ Wfc,
                                                 const float* __restrict__ bfc,
                                                 float* __restrict__ out) {
    int tid = threadIdx.x;
    int w = tid >> 5, lane = tid & 31;
    int row = blockIdx.x * 8 + w;
    const float* h = g_h1all + (size_t)row * DH;
    float a0 = 0.f, a1 = 0.f;
    for (int k = lane; k < DH; k += 32) {
        float hv = h[k];
        a0 += hv * Wfc[k * 2 + 0];
        a1 += hv * Wfc[k * 2 + 1];
    }
    #pragma unroll
    for (int off = 16; off; off >>= 1) {
        a0 += __shfl_xor_sync(0xFFFFFFFFu, a0, off);
        a1 += __shfl_xor_sync(0xFFFFFFFFu, a1, off);
    }
    if (lane == 0) {
        float l0 = a0 + bfc[0], l1 = a1 + bfc[1];
        float m  = fmaxf(l0, l1);
        float lse = m + logf(expf(l0 - m) + expf(l1 - m));
        int t = row >> 4, b = row & 15;
        out[((size_t)b * S + t) * 2 + 0] = l0 - lse;
        out[((size_t)b * S + t) * 2 + 1] = l1 - lse;
    }
}

// ---------------- launcher (graph-capturable, allocation-free) ----------------
extern "C" void kernel_launch(void* const* d_in, const int* in_sizes, int n_in,
                              void* d_out, int out_size) {
    const int*   tokens = (const int*)d_in[0];
    const float* emb    = (const float*)d_in[1];
    WPtrs p;
    for (int g = 0; g < 4; g++) {
        p.W0[g] = (const float*)d_in[2  + g * 2];
        p.b0[g] = (const float*)d_in[3  + g * 2];
        p.W1[g] = (const float*)d_in[10 + g * 2];
        p.b1[g] = (const float*)d_in[11 + g * 2];
    }
    const float* Wfc = (const float*)d_in[18];
    const float* bfc = (const float*)d_in[19];
    float* out = (float*)d_out;

    pack_kernel<<<(DH * NG + 255) / 256, 256>>>(p);
    packw_bf16_kernel<<<(NG * DIN + 255) / 256, 256>>>(p, 0);
    packw_bf16_kernel<<<(NG * DH  + 255) / 256, 256>>>(p, 1);

    // ----- layer 0 -----
    init_kernel<<<(3 * B * DH + 255) / 256, 256>>>();
    xcvt_kernel<<<(ROWS * DIN + 255) / 256, 256>>>(0, emb, tokens);
    mma_xpre_kernel<<<dim3(ROWS / 128, NG / 64), 256>>>(0);
    lstm_persist_kernel<<<NBLK, TPB>>>(0);

    // ----- layer 1 -----
    init_kernel<<<(3 * B * DH + 255) / 256, 256>>>();
    xcvt_kernel<<<(ROWS * DH + 255) / 256, 256>>>(1, emb, tokens);
    mma_xpre_kernel<<<dim3(ROWS / 128, NG / 64), 256>>>(1);
    lstm_persist_kernel<<<NBLK, TPB>>>(1);

    // ----- head -----
    fc_kernel<<<ROWS / 8, 256>>>(Wfc, bfc, out);
}

// round 9
// speedup vs baseline: 3.4891x; 1.5800x over previous
#include <cuda_runtime.h>
#include <cuda_bf16.h>
#include <math.h>
#include <stdint.h>

// Problem constants
#define B    16
#define S    512
#define DIN  512
#define DH   1024
#define NG   4096           // 4 gates * DH, gate-interleaved: n' = col*4 + gate
#define ROWS (B*S)          // 8192
#define NBLK 128            // persistent grid size
#define TPB  512            // threads per persistent block (16 warps)
#define WREC_SZ (128*16*4*4*2*32)   // 2,097,152 u32 per array

// ---------------- device scratch (static, allocation-free) ----------------
__device__ float g_b0p[NG];       // packed biases (gate-interleaved)
__device__ float g_b1p[NG];
// recurrent weights pre-packed into per-thread mma B-fragment layout (bf16x2 per u32)
__device__ uint32_t g_wrh0[WREC_SZ], g_wrl0[WREC_SZ];
__device__ uint32_t g_wrh1[WREC_SZ], g_wrl1[WREC_SZ];
// xpre input weights, K-major [n'][k], hi/lo
__device__ __nv_bfloat16 g_wbh0[(size_t)NG*DIN], g_wbl0[(size_t)NG*DIN];
__device__ __nv_bfloat16 g_wbh1[(size_t)NG*DH],  g_wbl1[(size_t)NG*DH];
__device__ __nv_bfloat16 g_xh[(size_t)ROWS*DH];   // X hi ([row][k], stride = layer K)
__device__ __nv_bfloat16 g_xl[(size_t)ROWS*DH];   // X lo
__device__ float g_xpre[(size_t)ROWS*NG];   // precomputed input-gate contributions
__device__ float g_h0all[(size_t)ROWS*DH];  // layer0 H for all t  [t*B+b][col]
__device__ float g_h1all[(size_t)ROWS*DH];  // layer1 H
// H state double-buffered, TRANSPOSED [k][b], bf16 hi/lo
__device__ __nv_bfloat16 g_hsbh[2][DH*B];
__device__ __nv_bfloat16 g_hsbl[2][DH*B];
__device__ float g_cstate[B*DH];            // C state
__device__ volatile unsigned g_bar;         // monotone grid-barrier counter

struct WPtrs {
    const float* W0[4]; const float* b0[4];
    const float* W1[4]; const float* b1[4];
};

// ================= warp-MMA helpers (sm_80+ PTX, legal on base sm_103) =================
__device__ __forceinline__ uint32_t smem_u32(const void* p) {
    uint32_t a;
    asm("{ .reg .u64 t; cvta.to.shared.u64 t, %1; cvt.u32.u64 %0, t; }" : "=r"(a) : "l"(p));
    return a;
}
__device__ __forceinline__ void ldm_x4(uint32_t* r, uint32_t addr) {
    asm volatile("ldmatrix.sync.aligned.m8n8.x4.shared.b16 {%0,%1,%2,%3}, [%4];"
                 : "=r"(r[0]), "=r"(r[1]), "=r"(r[2]), "=r"(r[3]) : "r"(addr));
}
__device__ __forceinline__ void ldm_x4_t(uint32_t* r, uint32_t addr) {
    asm volatile("ldmatrix.sync.aligned.m8n8.x4.trans.shared.b16 {%0,%1,%2,%3}, [%4];"
                 : "=r"(r[0]), "=r"(r[1]), "=r"(r[2]), "=r"(r[3]) : "r"(addr));
}
__device__ __forceinline__ void mma_bf16(float* d, const uint32_t* a, const uint32_t* b) {
    asm volatile("mma.sync.aligned.m16n8k16.row.col.f32.bf16.bf16.f32 "
                 "{%0,%1,%2,%3}, {%4,%5,%6,%7}, {%8,%9}, {%0,%1,%2,%3};"
                 : "+f"(d[0]), "+f"(d[1]), "+f"(d[2]), "+f"(d[3])
                 : "r"(a[0]), "r"(a[1]), "r"(a[2]), "r"(a[3]), "r"(b[0]), "r"(b[1]));
}
static __device__ __forceinline__ uint32_t sw128(uint32_t x) { return x ^ ((x >> 3) & 0x70); }

// ---------------- bias packing ----------------
__global__ void packb_kernel(WPtrs p) {
    int np = blockIdx.x * blockDim.x + threadIdx.x;
    if (np >= NG) return;
    int col = np >> 2, g = np & 3;
    g_b0p[np] = p.b0[g][col];
    g_b1p[np] = p.b1[g][col];
}

// ---------------- recurrent weight pack: per-thread mma B-fragment layout ----------------
// idx = ((((bx*16+w)*4 + s)*4 + nt)*2 + r)*32 + lane
// n' = bx*32 + nt*8 + (lane>>2);  k = w*64 + s*16 + r*8 + (lane&3)*2  (pair k, k+1)
__global__ void packw_rec_kernel(WPtrs p, int layer) {
    int tid = blockIdx.x * blockDim.x + threadIdx.x;
    if (tid >= WREC_SZ) return;
    int lane = tid & 31;
    int r    = (tid >> 5) & 1;
    int nt   = (tid >> 6) & 3;
    int s    = (tid >> 8) & 3;
    int w    = (tid >> 10) & 15;
    int bx   = tid >> 14;
    int np  = bx * 32 + nt * 8 + (lane >> 2);
    int col = np >> 2, g = np & 3;
    int k   = w * 64 + s * 16 + r * 8 + (lane & 3) * 2;
    const float* W = layer ? p.W1[g] : p.W0[g];
    const int Koff = layer ? DH : DIN;
    float w0 = W[(size_t)(Koff + k) * DH + col];
    float w1 = W[(size_t)(Koff + k + 1) * DH + col];
    __nv_bfloat16 h0 = __float2bfloat16(w0), h1 = __float2bfloat16(w1);
    __nv_bfloat16 l0 = __float2bfloat16(w0 - __bfloat162float(h0));
    __nv_bfloat16 l1 = __float2bfloat16(w1 - __bfloat162float(h1));
    uint32_t hp = (uint32_t)__bfloat16_as_ushort(h0) | ((uint32_t)__bfloat16_as_ushort(h1) << 16);
    uint32_t lp = (uint32_t)__bfloat16_as_ushort(l0) | ((uint32_t)__bfloat16_as_ushort(l1) << 16);
    if (layer) { g_wrh1[tid] = hp; g_wrl1[tid] = lp; }
    else       { g_wrh0[tid] = hp; g_wrl0[tid] = lp; }
}

// ---------------- bf16 hi/lo pack of xpre input weights, K-major [n'][k] ----------------
__global__ void packw_bf16_kernel(WPtrs p, int layer) {
    const int K = layer ? DH : DIN;
    int tid = blockIdx.x * blockDim.x + threadIdx.x;
    if (tid >= NG * K) return;
    int np = tid / K, k = tid % K;
    int col = np >> 2, g = np & 3;
    float w = layer ? p.W1[g][k * DH + col] : p.W0[g][k * DH + col];
    __nv_bfloat16 hi = __float2bfloat16(w);
    __nv_bfloat16 lo = __float2bfloat16(w - __bfloat162float(hi));
    if (layer) { g_wbh1[tid] = hi; g_wbl1[tid] = lo; }
    else       { g_wbh0[tid] = hi; g_wbl0[tid] = lo; }
}

// ---------------- X hi/lo conversion ----------------
__global__ void xcvt_kernel(int layer, const float* __restrict__ emb,
                            const int* __restrict__ tokens) {
    const int K = layer ? DH : DIN;
    long long tid = (long long)blockIdx.x * blockDim.x + threadIdx.x;
    if (tid >= (long long)ROWS * K) return;
    int row = (int)(tid / K), k = (int)(tid % K);
    float v;
    if (layer == 0) {
        int b = row & 15, t = row >> 4;
        v = emb[(size_t)tokens[b * S + t] * DIN + k];
    } else {
        v = g_h0all[(size_t)row * DH + k];
    }
    __nv_bfloat16 hi = __float2bfloat16(v);
    __nv_bfloat16 lo = __float2bfloat16(v - __bfloat162float(hi));
    g_xh[(size_t)row * K + k] = hi;
    g_xl[(size_t)row * K + k] = lo;
}

// ---------------- zero H / C state + barrier counter ----------------
__global__ void init_kernel() {
    int tid = blockIdx.x * blockDim.x + threadIdx.x;
    if (tid < 16384)            ((uint32_t*)g_hsbh)[tid] = 0u;       // 2 bufs x 16384 bf16
    else if (tid < 32768)       ((uint32_t*)g_hsbl)[tid - 16384] = 0u;
    else if (tid < 32768 + B*DH) g_cstate[tid - 32768] = 0.f;
    if (tid == 0) g_bar = 0u;
}

// ---------------- HMMA xpre GEMM: g_xpre = bias + X @ Wx (bf16 hi/lo x3) ----------------
__global__ void __launch_bounds__(256) mma_xpre_kernel(int layer) {
    __shared__ __align__(128) char sAraw[128 * 128];
    __shared__ __align__(128) char sBraw[64 * 128];

    const int K = layer ? DH : DIN;
    const __nv_bfloat16* Wh = layer ? g_wbh1 : g_wbh0;
    const __nv_bfloat16* Wl = layer ? g_wbl1 : g_wbl0;
    const float* biasp = layer ? g_b1p : g_b0p;

    const int tid  = threadIdx.x, wid = tid >> 5, lane = tid & 31;
    const int rbase = blockIdx.x * 128;
    const int nbase = blockIdx.y * 64;
    const int wm = wid >> 1, wn = wid & 1;

    const uint32_t sAb = smem_u32(sAraw), sBb = smem_u32(sBraw);

    const int ra0 = wm * 32 + (lane & 7) + (lane & 8);
    const int rb0 = wn * 32 + (lane & 7) + (((lane >> 4) & 1) * 8);
    const int ua  = (lane >> 4);
    const int ub  = ((lane >> 3) & 1);

    float acc[2][4][4];
    #pragma unroll
    for (int i = 0; i < 2; i++)
        #pragma unroll
        for (int j = 0; j < 4; j++)
            #pragma unroll
            for (int q = 0; q < 4; q++) acc[i][j][q] = 0.f;

    const int nch = K / 64;
    const int total = 3 * nch;

    uint4 xr[4], wr[2];
    {
        #pragma unroll
        for (int j = 0; j < 4; j++) {
            int gidx = j * 256 + tid, r = gidx >> 3, kg = gidx & 7;
            xr[j] = *(const uint4*)(g_xh + (size_t)(rbase + r) * K + kg * 8);
        }
        #pragma unroll
        for (int j = 0; j < 2; j++) {
            int gidx = j * 256 + tid, r = gidx >> 3, kg = gidx & 7;
            wr[j] = *(const uint4*)(Wh + (size_t)(nbase + r) * K + kg * 8);
        }
    }

    int p = 0, kc = 0;
    for (int it = 0; it < total; it++) {
        #pragma unroll
        for (int j = 0; j < 4; j++) {
            int gidx = j * 256 + tid, r = gidx >> 3, kg = gidx & 7;
            *(uint4*)(sAraw + sw128((uint32_t)(r * 128 + kg * 16))) = xr[j];
        }
        #pragma unroll
        for (int j = 0; j < 2; j++) {
            int gidx = j * 256 + tid, r = gidx >> 3, kg = gidx & 7;
            *(uint4*)(sBraw + sw128((uint32_t)(r * 128 + kg * 16))) = wr[j];
        }
        __syncthreads();

        int np2 = p, nkc = kc + 1;
        if (nkc == nch) { nkc = 0; np2 = p + 1; }
        if (it + 1 < total) {
            const __nv_bfloat16* Asrc = (np2 == 1) ? g_xl : g_xh;
            const __nv_bfloat16* Bsrc = (np2 == 2) ? Wl : Wh;
            const int koff = nkc * 64;
            #pragma unroll
            for (int j = 0; j < 4; j++) {
                int gidx = j * 256 + tid, r = gidx >> 3, kg = gidx & 7;
                xr[j] = *(const uint4*)(Asrc + (size_t)(rbase + r) * K + koff + kg * 8);
            }
            #pragma unroll
            for (int j = 0; j < 2; j++) {
                int gidx = j * 256 + tid, r = gidx >> 3, kg = gidx & 7;
                wr[j] = *(const uint4*)(Bsrc + (size_t)(nbase + r) * K + koff + kg * 8);
            }
        }

        #pragma unroll
        for (int s = 0; s < 4; s++) {
            uint32_t a0[4], a1[4], b0[4], b1[4];
            ldm_x4(a0, sAb + sw128((uint32_t)( ra0       * 128 + (s * 2 + ua) * 16)));
            ldm_x4(a1, sAb + sw128((uint32_t)((ra0 + 16) * 128 + (s * 2 + ua) * 16)));
            ldm_x4(b0, sBb + sw128((uint32_t)( rb0       * 128 + (s * 2 + ub) * 16)));
            ldm_x4(b1, sBb + sw128((uint32_t)((rb0 + 16) * 128 + (s * 2 + ub) * 16)));
            mma_bf16(acc[0][0], a0, b0 + 0);
            mma_bf16(acc[0][1], a0, b0 + 2);
            mma_bf16(acc[0][2], a0, b1 + 0);
            mma_bf16(acc[0][3], a0, b1 + 2);
            mma_bf16(acc[1][0], a1, b0 + 0);
            mma_bf16(acc[1][1], a1, b0 + 2);
            mma_bf16(acc[1][2], a1, b1 + 0);
            mma_bf16(acc[1][3], a1, b1 + 2);
        }
        __syncthreads();
        p = np2; kc = nkc;
    }

    #pragma unroll
    for (int mt = 0; mt < 2; mt++) {
        #pragma unroll
        for (int nt = 0; nt < 4; nt++) {
            int r = rbase + wm * 32 + mt * 16 + (lane >> 2);
            int c = nbase + wn * 32 + nt * 8 + (lane & 3) * 2;
            float bv0 = biasp[c], bv1 = biasp[c + 1];
            float2 o0 = make_float2(acc[mt][nt][0] + bv0, acc[mt][nt][1] + bv1);
            float2 o1 = make_float2(acc[mt][nt][2] + bv0, acc[mt][nt][3] + bv1);
            *(float2*)(g_xpre + (size_t)r * NG + c)       = o0;
            *(float2*)(g_xpre + (size_t)(r + 8) * NG + c) = o1;
        }
    }
}

// ---------------- persistent recurrent layer: HMMA, weights-stationary fragments ----------------
// 128 blocks x 512 threads (16 warps). Block bx owns n' [bx*32, +32); warp w owns k-slice
// [w*64, +64). B fragments (hi/lo) preloaded once into 64 regs/thread. Per step: warp
// stages its H slice (bf16 hi/lo, [k][b]) into 4KB warp-private smem, ldmatrix.trans for A,
// 48 mma (hi*hi + lo*hi + hi*lo), fragment dump into warp-private smem, cross-warp sum +
// LSTM finalize on 128 threads, one grid barrier.
__global__ void __launch_bounds__(TPB) lstm_persist_kernel(int layer) {
    __shared__ __align__(16) char ssm[16 * 4096];   // 64KB: per-warp 4KB (A hi | A lo / reduce)

    const uint32_t* Wh = layer ? g_wrh1 : g_wrh0;
    const uint32_t* Wl = layer ? g_wrl1 : g_wrl0;
    float* hall_base   = layer ? g_h1all : g_h0all;

    const int tid  = threadIdx.x;
    const int w    = tid >> 5, lane = tid & 31;
    const int bx   = blockIdx.x;
    const int col0 = bx * 8;

    // ---- preload B fragments (one-time): bh/bl[s][nt][r] ----
    uint32_t bh[4][4][2], bl[4][4][2];
    {
        int base = (bx * 16 + w) * 16384 / 16;   // = (bx*16+w)*1024
        #pragma unroll
        for (int s = 0; s < 4; s++)
            #pragma unroll
            for (int nt = 0; nt < 4; nt++)
                #pragma unroll
                for (int r = 0; r < 2; r++) {
                    int idx = base + s * 256 + nt * 64 + r * 32 + lane;
                    bh[s][nt][r] = Wh[idx];
                    bl[s][nt][r] = Wl[idx];
                }
    }

    // ldmatrix.trans addressing within warp A region ([k_local][b], 32B rows)
    const uint32_t sW  = smem_u32(ssm) + w * 4096;      // hi base; lo = +2048
    const uint32_t aoff = (uint32_t)(((lane & 7) + ((lane >> 4) << 3)) * 32 + ((lane >> 3) & 1) * 16);

    for (int t = 0; t < S; t++) {
        const int cur = t & 1, nxt = cur ^ 1;

        // ---- stage this warp's H slice: 2KB hi + 2KB lo, contiguous, warp-private ----
        {
            const uint4* srcH = (const uint4*)(g_hsbh[cur] + w * 1024);
            const uint4* srcL = (const uint4*)(g_hsbl[cur] + w * 1024);
            uint4* dH = (uint4*)(ssm + w * 4096);
            uint4* dL = (uint4*)(ssm + w * 4096 + 2048);
            #pragma unroll
            for (int j = 0; j < 4; j++) {
                dH[lane + j * 32] = __ldcg(srcH + lane + j * 32);
                dL[lane + j * 32] = __ldcg(srcL + lane + j * 32);
            }
        }
        __syncwarp();

        // ---- compute: 4 k16-steps x 4 n8-tiles x 3 passes ----
        float acc[4][4];
        #pragma unroll
        for (int nt = 0; nt < 4; nt++)
            #pragma unroll
            for (int q = 0; q < 4; q++) acc[nt][q] = 0.f;

        #pragma unroll
        for (int s = 0; s < 4; s++) {
            uint32_t ah[4], al[4];
            ldm_x4_t(ah, sW + s * 512 + aoff);
            ldm_x4_t(al, sW + 2048 + s * 512 + aoff);
            #pragma unroll
            for (int nt = 0; nt < 4; nt++) {
                mma_bf16(acc[nt], ah, bh[s][nt]);
                mma_bf16(acc[nt], al, bh[s][nt]);
                mma_bf16(acc[nt], ah, bl[s][nt]);
            }
        }
        __syncwarp();

        // ---- dump fragments into warp-private reduce region (stride 36 floats) ----
        {
            float* rb = (float*)(ssm + w * 4096);
            int m0 = lane >> 2, n0 = (lane & 3) * 2;
            #pragma unroll
            for (int nt = 0; nt < 4; nt++) {
                *(float2*)(rb + m0 * 36 + nt * 8 + n0)       = make_float2(acc[nt][0], acc[nt][1]);
                *(float2*)(rb + (m0 + 8) * 36 + nt * 8 + n0) = make_float2(acc[nt][2], acc[nt][3]);
            }
        }
        __syncthreads();

        // ---- finalize: 128 threads, (b = tid&15, cl = tid>>4) ----
        if (tid < 128) {
            int b = tid & 15, cl = tid >> 4;
            const float* xq = g_xpre + ((size_t)t * B + b) * NG + bx * 32;
            float ga[4];
            #pragma unroll
            for (int g = 0; g < 4; g++) {
                int nloc = cl * 4 + g;
                float v = xq[nloc];
                #pragma unroll
                for (int ww = 0; ww < 16; ww++)
                    v += ((const float*)(ssm + ww * 4096))[b * 36 + nloc];
                ga[g] = v;
            }
            float I = 1.f / (1.f + expf(-ga[0]));
            float F = 1.f / (1.f + expf(-ga[1]));
            float G = tanhf(ga[2]);
            float O = 1.f / (1.f + expf(-ga[3]));
            int col = col0 + cl;
            int ci  = b * DH + col;
            float C = F * g_cstate[ci] + I * G;
            g_cstate[ci] = C;
            float H = O * tanhf(C);
            __nv_bfloat16 hi = __float2bfloat16(H);
            __nv_bfloat16 lo = __float2bfloat16(H - __bfloat162float(hi));
            g_hsbh[nxt][col * 16 + b] = hi;
            g_hsbl[nxt][col * 16 + b] = lo;
            hall_base[((size_t)t * B + b) * DH + col] = H;
            __threadfence();
        }

        // ---- grid barrier (monotone counter) ----
        __syncthreads();
        if (tid == 0) {
            __threadfence();
            atomicAdd((unsigned*)&g_bar, 1u);
            unsigned target = (unsigned)(t + 1) * NBLK;
            while (g_bar < target) { }
            __threadfence();
        }
        __syncthreads();
    }
}

// ---------------- FC head + 2-class log_softmax ----------------
__global__ void __launch_bounds__(256) fc_kernel(const float* __restrict__ Wfc,
                                                 const float* __restrict__ bfc,
                                                 float* __restrict__ out) {
    int tid = threadIdx.x;
    int w = tid >> 5, lane = tid & 31;
    int row = blockIdx.x * 8 + w;
    const float* h = g_h1all + (size_t)row * DH;
    float a0 = 0.f, a1 = 0.f;
    for (int k = lane; k < DH; k += 32) {
        float hv = h[k];
        a0 += hv * Wfc[k * 2 + 0];
        a1 += hv * Wfc[k * 2 + 1];
    }
    #pragma unroll
    for (int off = 16; off; off >>= 1) {
        a0 += __shfl_xor_sync(0xFFFFFFFFu, a0, off);
        a1 += __shfl_xor_sync(0xFFFFFFFFu, a1, off);
    }
    if (lane == 0) {
        float l0 = a0 + bfc[0], l1 = a1 + bfc[1];
        float m  = fmaxf(l0, l1);
        float lse = m + logf(expf(l0 - m) + expf(l1 - m));
        int t = row >> 4, b = row & 15;
        out[((size_t)b * S + t) * 2 + 0] = l0 - lse;
        out[((size_t)b * S + t) * 2 + 1] = l1 - lse;
    }
}

// ---------------- launcher (graph-capturable, allocation-free) ----------------
extern "C" void kernel_launch(void* const* d_in, const int* in_sizes, int n_in,
                              void* d_out, int out_size) {
    const int*   tokens = (const int*)d_in[0];
    const float* emb    = (const float*)d_in[1];
    WPtrs p;
    for (int g = 0; g < 4; g++) {
        p.W0[g] = (const float*)d_in[2  + g * 2];
        p.b0[g] = (const float*)d_in[3  + g * 2];
        p.W1[g] = (const float*)d_in[10 + g * 2];
        p.b1[g] = (const float*)d_in[11 + g * 2];
    }
    const float* Wfc = (const float*)d_in[18];
    const float* bfc = (const float*)d_in[19];
    float* out = (float*)d_out;

    packb_kernel<<<(NG + 255) / 256, 256>>>(p);
    packw_rec_kernel<<<WREC_SZ / 256, 256>>>(p, 0);
    packw_rec_kernel<<<WREC_SZ / 256, 256>>>(p, 1);
    packw_bf16_kernel<<<(NG * DIN + 255) / 256, 256>>>(p, 0);
    packw_bf16_kernel<<<(NG * DH  + 255) / 256, 256>>>(p, 1);

    // ----- layer 0 -----
    init_kernel<<<192, 256>>>();
    xcvt_kernel<<<(ROWS * DIN + 255) / 256, 256>>>(0, emb, tokens);
    mma_xpre_kernel<<<dim3(ROWS / 128, NG / 64), 256>>>(0);
    lstm_persist_kernel<<<NBLK, TPB>>>(0);

    // ----- layer 1 -----
    init_kernel<<<192, 256>>>();
    xcvt_kernel<<<(ROWS * DH + 255) / 256, 256>>>(1, emb, tokens);
    mma_xpre_kernel<<<dim3(ROWS / 128, NG / 64), 256>>>(1);
    lstm_persist_kernel<<<NBLK, TPB>>>(1);

    // ----- head -----
    fc_kernel<<<ROWS / 8, 256>>>(Wfc, bfc, out);
}